// round 16
// baseline (speedup 1.0000x reference)
#include <cuda_runtime.h>
#include <cuda_bf16.h>
#include <cstdint>

typedef unsigned long long ull;

#define MAXT 66560
#define MAXB 2048

// Scratch (static device allocations — no cudaMalloc allowed)
__device__ float         g_qkv[(size_t)MAXT * 384];
__device__ __nv_bfloat16 g_ah[(size_t)MAXT * 128];
__device__ __nv_bfloat16 g_al[(size_t)MAXT * 128];
__device__ __nv_bfloat16 g_oh[(size_t)MAXT * 128];
__device__ __nv_bfloat16 g_ol[(size_t)MAXT * 128];
__device__ __nv_bfloat16 g_wh1[384 * 128];
__device__ __nv_bfloat16 g_wl1[384 * 128];
__device__ __nv_bfloat16 g_wh2[128 * 128];
__device__ __nv_bfloat16 g_wl2[128 * 128];
__device__ int           g_offs[MAXB];

// ---------------------------------------------------------------------------
// helpers
// ---------------------------------------------------------------------------
__device__ __forceinline__ uint32_t smem_u32(const void* p) {
    uint32_t a;
    asm("{ .reg .u64 t; cvta.to.shared.u64 t, %1; cvt.u32.u64 %0, t; }" : "=r"(a) : "l"(p));
    return a;
}
__device__ __forceinline__ void cp16(uint32_t s, const void* g) {
    asm volatile("cp.async.ca.shared.global [%0], [%1], 16;" :: "r"(s), "l"(g));
}
#define CP_COMMIT() asm volatile("cp.async.commit_group;" ::: "memory")
#define CP_WAIT0()  asm volatile("cp.async.wait_group 0;" ::: "memory")
#define CP_WAIT1()  asm volatile("cp.async.wait_group 1;" ::: "memory")

__device__ __forceinline__ float bf2f_us(unsigned short u) {
    return __bfloat162float(__ushort_as_bfloat16(u));
}
__device__ __forceinline__ unsigned short f2bf_us(float x) {
    return __bfloat16_as_ushort(__float2bfloat16(x));
}
__device__ __forceinline__ uint32_t bfpack2f(float x, float y) {
    return (uint32_t)f2bf_us(x) | ((uint32_t)f2bf_us(y) << 16);
}

// bf16 hi/lo split of a float4 -> two packed 8-byte values
__device__ __forceinline__ void split4(float4 v, ull& hp, ull& lp) {
    unsigned short hx = f2bf_us(v.x), hy = f2bf_us(v.y), hz = f2bf_us(v.z), hw = f2bf_us(v.w);
    hp = (ull)hx | ((ull)hy << 16) | ((ull)hz << 32) | ((ull)hw << 48);
    unsigned short lx = f2bf_us(v.x - bf2f_us(hx));
    unsigned short ly = f2bf_us(v.y - bf2f_us(hy));
    unsigned short lz = f2bf_us(v.z - bf2f_us(hz));
    unsigned short lw = f2bf_us(v.w - bf2f_us(hw));
    lp = (ull)lx | ((ull)ly << 16) | ((ull)lz << 32) | ((ull)lw << 48);
}

__device__ __forceinline__ void ldm_x4(uint32_t* r, uint32_t addr) {
    asm volatile("ldmatrix.sync.aligned.m8n8.x4.shared.b16 {%0,%1,%2,%3}, [%4];"
                 : "=r"(r[0]), "=r"(r[1]), "=r"(r[2]), "=r"(r[3]) : "r"(addr));
}
__device__ __forceinline__ void ldm_x4_trans(uint32_t* r, uint32_t addr) {
    asm volatile("ldmatrix.sync.aligned.m8n8.x4.trans.shared.b16 {%0,%1,%2,%3}, [%4];"
                 : "=r"(r[0]), "=r"(r[1]), "=r"(r[2]), "=r"(r[3]) : "r"(addr));
}
__device__ __forceinline__ void mma_bf16(float* d, const uint32_t* a, const uint32_t* b) {
    asm volatile("mma.sync.aligned.m16n8k16.row.col.f32.bf16.bf16.f32 "
                 "{%0,%1,%2,%3}, {%4,%5,%6,%7}, {%8,%9}, {%0,%1,%2,%3};"
                 : "+f"(d[0]), "+f"(d[1]), "+f"(d[2]), "+f"(d[3])
                 : "r"(a[0]), "r"(a[1]), "r"(a[2]), "r"(a[3]), "r"(b[0]), "r"(b[1]));
}

// ---------------------------------------------------------------------------
// Prep kernel (ONE launch):
//   blocks [0, nact)          : convert att_in fp32 -> g_ah/g_al planes
//   blocks [nact, nact+48)    : convert in_proj_w   -> g_wh1/g_wl1
//   blocks [nact+48, nact+64) : convert out_proj_w  -> g_wh2/g_wl2
//   block  nact+64            : exclusive prefix sum -> g_offs
// ---------------------------------------------------------------------------
__global__ void prep_kernel(const float* __restrict__ att_in,
                            const float* __restrict__ w1,
                            const float* __restrict__ w2,
                            const int* __restrict__ agents, int B, int T,
                            int nact)
{
    int bid = blockIdx.x;
    int tid = threadIdx.x;

    if (bid < nact) {
        int i = bid * 256 + tid;
        if (i < T * 32) {
            float4 v = ((const float4*)att_in)[i];
            ull hp, lp;
            split4(v, hp, lp);
            *(ull*)(g_ah + (size_t)i * 4) = hp;
            *(ull*)(g_al + (size_t)i * 4) = lp;
        }
        return;
    }
    int wb = bid - nact;
    if (wb < 64) {
        const float* src;
        __nv_bfloat16 *dh, *dl;
        int i;
        if (wb < 48) {
            src = w1; dh = g_wh1; dl = g_wl1;
            i = wb * 256 + tid;
        } else {
            src = w2; dh = g_wh2; dl = g_wl2;
            i = (wb - 48) * 256 + tid;
        }
        float4 v = ((const float4*)src)[i];
        ull hp, lp;
        split4(v, hp, lp);
        *(ull*)(dh + (size_t)i * 4) = hp;
        *(ull*)(dl + (size_t)i * 4) = lp;
        return;
    }

    // ---- scan ----
    __shared__ int part[256];
    int local[8];
    int s = 0;
#pragma unroll
    for (int i = 0; i < 8; i++) {
        int idx = tid * 8 + i;
        local[i] = (idx < B) ? agents[idx] : 0;
        s += local[i];
    }
    part[tid] = s;
    __syncthreads();
    for (int d = 1; d < 256; d <<= 1) {
        int v = (tid >= d) ? part[tid - d] : 0;
        __syncthreads();
        part[tid] += v;
        __syncthreads();
    }
    int base = (tid > 0) ? part[tid - 1] : 0;
#pragma unroll
    for (int i = 0; i < 8; i++) {
        int idx = tid * 8 + i;
        if (idx < B) g_offs[idx] = base;
        base += local[i];
    }
}

// ---------------------------------------------------------------------------
// Persistent GEMM (r12, proven config): 64x128 CTA tile, W slice loaded once,
// double-buffered A tiles, warp tile 32x32. 3-term: Ah*Wh + Ah*Wl + Al*Wh.
// ---------------------------------------------------------------------------
#define ASTRIDE 136                  // bf16 elems per smem row (272B)
#define SA0_H 0
#define SA0_L 17408
#define SA1_H 34816
#define SA1_L 52224
#define SW_H  69632
#define SW_L  104448
#define GEMM_SMEM 139264

__device__ __forceinline__ void fill_a(uint32_t sb, uint32_t off_h, uint32_t off_l,
                                       const __nv_bfloat16* Ah, const __nv_bfloat16* Al,
                                       int bm, int tid)
{
#pragma unroll
    for (int t = 0; t < 4; t++) {
        int c = tid + t * 256;           // 0..1023
        int row = c >> 4, c16 = c & 15;
        uint32_t so = (uint32_t)(row * 272 + c16 * 16);
        cp16(sb + off_h + so, (const char*)(Ah + (size_t)(bm + row) * 128) + c16 * 16);
        cp16(sb + off_l + so, (const char*)(Al + (size_t)(bm + row) * 128) + c16 * 16);
    }
}

__global__ __launch_bounds__(256) void gemm_tc_kernel(
    const __nv_bfloat16* __restrict__ Ah_g, const __nv_bfloat16* __restrict__ Al_g,
    const __nv_bfloat16* __restrict__ Wh, const __nv_bfloat16* __restrict__ Wl,
    const float* __restrict__ bias, float* __restrict__ C, int N, int ntiles)
{
    extern __shared__ char sm[];
    const uint32_t sb = smem_u32(sm);
    const int tid  = threadIdx.x;
    const int wid  = tid >> 5;
    const int lane = tid & 31;
    const int bn   = blockIdx.y * 128;
    const int t0     = blockIdx.x;
    const int stride = gridDim.x;

    // ---- W slice (128 rows, hi+lo) once ----
#pragma unroll
    for (int t = 0; t < 8; t++) {
        int c = tid + t * 256;           // 0..2047
        int row = c >> 4, c16 = c & 15;
        uint32_t so = (uint32_t)(row * 272 + c16 * 16);
        cp16(sb + SW_H + so, (const char*)(Wh + (size_t)(bn + row) * 128) + c16 * 16);
        cp16(sb + SW_L + so, (const char*)(Wl + (size_t)(bn + row) * 128) + c16 * 16);
    }
    if (t0 < ntiles)
        fill_a(sb, SA0_H, SA0_L, Ah_g, Al_g, t0 * 64, tid);
    CP_COMMIT();

    const int wm = (wid & 1) * 32;
    const int wn = (wid >> 1) * 32;
    const int arow = wm + (lane & 15);
    const int acol8 = (lane >> 4) * 8;
    const int bgrp = lane >> 3;
    const int brow0 = wn + ((bgrp >> 1) << 3) + (lane & 7);
    const int bk8   = (bgrp & 1) << 3;
    const int er = lane >> 2;
    const int ec = (lane & 3) * 2;

    float bb0[4], bb1[4];
#pragma unroll
    for (int ni = 0; ni < 4; ni++) {
        int n = bn + wn + ni * 8 + ec;
        bb0[ni] = bias[n];
        bb1[ni] = bias[n + 1];
    }

    int buf = 0;
    for (int t = t0; t < ntiles; t += stride) {
        int tn = t + stride;
        if (tn < ntiles) {
            fill_a(sb, buf ? SA0_H : SA1_H, buf ? SA0_L : SA1_L,
                   Ah_g, Al_g, tn * 64, tid);
            CP_COMMIT();
            CP_WAIT1();
        } else {
            CP_WAIT0();
        }
        __syncthreads();

        const uint32_t sa_h = buf ? SA1_H : SA0_H;
        const uint32_t sa_l = buf ? SA1_L : SA0_L;

        float acc[2][4][4];
#pragma unroll
        for (int mi = 0; mi < 2; mi++)
#pragma unroll
            for (int ni = 0; ni < 4; ni++)
#pragma unroll
                for (int e = 0; e < 4; e++) acc[mi][ni][e] = 0.f;

#pragma unroll
        for (int k = 0; k < 8; k++) {
            const int kb = k * 16;
            uint32_t ahf[2][4], alf[2][4];
#pragma unroll
            for (int mi = 0; mi < 2; mi++) {
                uint32_t off = (uint32_t)(((arow + mi * 16) * ASTRIDE + kb + acol8) * 2);
                ldm_x4(ahf[mi], sb + sa_h + off);
                ldm_x4(alf[mi], sb + sa_l + off);
            }
            uint32_t bhf[4][2], blf[4][2];
#pragma unroll
            for (int nip = 0; nip < 2; nip++) {
                uint32_t off = (uint32_t)(((brow0 + nip * 16) * ASTRIDE + kb + bk8) * 2);
                ldm_x4(&bhf[nip * 2][0], sb + SW_H + off);
                ldm_x4(&blf[nip * 2][0], sb + SW_L + off);
            }
#pragma unroll
            for (int mi = 0; mi < 2; mi++)
#pragma unroll
                for (int ni = 0; ni < 4; ni++) {
                    mma_bf16(acc[mi][ni], ahf[mi], bhf[ni]);
                    mma_bf16(acc[mi][ni], ahf[mi], blf[ni]);
                    mma_bf16(acc[mi][ni], alf[mi], bhf[ni]);
                }
        }

        const int bm = t * 64;
#pragma unroll
        for (int ni = 0; ni < 4; ni++) {
            int n = bn + wn + ni * 8 + ec;
#pragma unroll
            for (int mi = 0; mi < 2; mi++) {
                int m0 = bm + wm + mi * 16 + er;
                *(float2*)(C + (size_t)m0 * N + n) =
                    make_float2(acc[mi][ni][0] + bb0[ni], acc[mi][ni][1] + bb1[ni]);
                *(float2*)(C + (size_t)(m0 + 8) * N + n) =
                    make_float2(acc[mi][ni][2] + bb0[ni], acc[mi][ni][3] + bb1[ni]);
            }
        }
        __syncthreads();
        buf ^= 1;
    }
}

// ---------------------------------------------------------------------------
// Attention v8 (tensor core): block = sample (512 thr, 16 warps),
// warp = (head, 32-query half). K AND V stored [key][d] bf16 hi/lo
// (vectorized fill, NO transpose scatter). QK^T B-frags via ldmatrix,
// P*V B-frags via ldmatrix.trans (HW transposes V tiles during load).
// C-frag == A-frag layout -> packed P (hi/lo) feeds P*V MMA directly.
// ---------------------------------------------------------------------------
#define KROW   48                    // bytes per row (16 bf16 = 32B + 16B pad)
#define KPLANE 3072                  // 64 * KROW
#define HEADSZ (4 * KPLANE)          // Kh,Kl,Vh,Vl = 12288
#define ATTN_SMEM (8 * HEADSZ)       // 98304

__global__ __launch_bounds__(512, 1) void attn_kernel(
    const float* __restrict__ Y,            // qkv [T][384]
    __nv_bfloat16* __restrict__ Oh,         // attn out hi plane [T][128]
    __nv_bfloat16* __restrict__ Ol,         // attn out lo plane [T][128]
    const int* __restrict__ agents, int B)
{
    extern __shared__ char smc[];
    const uint32_t sb = smem_u32(smc);
    int b = blockIdx.x;
    if (B == 2048) {                         // largest-first schedule
        int g = b >> 5, k = b & 31;
        b = (k << 6) + (63 - g);
    }
    const int n   = agents[b];
    const int o   = g_offs[b];
    const int tid = threadIdx.x;

    // ---- fill: thread t -> (head = t>>6, row = t&63); K and V identical ----
    {
        int fh = tid >> 6, row = tid & 63;
        char* hb = smc + fh * HEADSZ;
        const float* yr = Y + (size_t)(o + row) * 384 + fh * 16;
#pragma unroll
        for (int s = 0; s < 4; s++) {
            float4 kv = (row < n) ? *(const float4*)(yr + 128 + s * 4)
                                  : make_float4(0.f, 0.f, 0.f, 0.f);
            ull hp, lp;
            split4(kv, hp, lp);
            *(ull*)(hb + row * KROW + s * 8)          = hp;   // Kh
            *(ull*)(hb + KPLANE + row * KROW + s * 8) = lp;   // Kl
            float4 vv = (row < n) ? *(const float4*)(yr + 256 + s * 4)
                                  : make_float4(0.f, 0.f, 0.f, 0.f);
            split4(vv, hp, lp);
            *(ull*)(hb + 2 * KPLANE + row * KROW + s * 8) = hp;   // Vh
            *(ull*)(hb + 3 * KPLANE + row * KROW + s * 8) = lp;   // Vl
        }
    }
    __syncthreads();

    const int wid  = tid >> 5;
    const int lane = tid & 31;
    const int h    = wid & 7;
    const int mh   = wid >> 3;               // query half
    if (mh && n <= 32) return;

    const uint32_t khb = sb + h * HEADSZ;
    const uint32_t klb = khb + KPLANE;
    const uint32_t vhb = khb + 2 * KPLANE;
    const uint32_t vlb = khb + 3 * KPLANE;

    const int qbase = mh * 32;
    const int r0l   = lane >> 2;             // row within m16 tile
    const int kc0   = (lane & 3) * 2;        // col pair base

    // ---- Q fragments from gmem (scaled 0.25), bf16 hi/lo ----
    uint32_t qh[2][4], ql[2][4];
#pragma unroll
    for (int mt = 0; mt < 2; mt++) {
#pragma unroll
        for (int a = 0; a < 4; a++) {
            int row = qbase + mt * 16 + r0l + ((a & 1) ? 8 : 0);
            int col = kc0 + ((a >= 2) ? 8 : 0);
            float2 x = make_float2(0.f, 0.f);
            if (row < n) x = *(const float2*)(Y + (size_t)(o + row) * 384 + h * 16 + col);
            x.x *= 0.25f; x.y *= 0.25f;
            unsigned short hx = f2bf_us(x.x), hy = f2bf_us(x.y);
            qh[mt][a] = (uint32_t)hx | ((uint32_t)hy << 16);
            ql[mt][a] = bfpack2f(x.x - bf2f_us(hx), x.y - bf2f_us(hy));
        }
    }

    float oacc[2][2][4];
#pragma unroll
    for (int mt = 0; mt < 2; mt++)
#pragma unroll
        for (int dt = 0; dt < 2; dt++)
#pragma unroll
            for (int e = 0; e < 4; e++) oacc[mt][dt][e] = 0.f;
    float rs[2][2] = {{0.f, 0.f}, {0.f, 0.f}};

    const int bgrp     = lane >> 3;
    const int brow_off = ((bgrp >> 1) << 3) + (lane & 7);   // K (non-trans) addressing
    const int bk8      = (bgrp & 1) << 3;
    const int vrow_off = ((bgrp & 1) << 3) + (lane & 7);    // V (trans) addressing
    const int vd16     = (bgrp >> 1) << 4;                  // d byte offset (8 bf16)

    const int nsh = (n > 32) ? 2 : 1;
    for (int sh = 0; sh < nsh; sh++) {
        const int kb = sh * 32;

        // ---- scores S[q, kb..kb+31] via 3-term MMA ----
        float sacc[2][4][4];
#pragma unroll
        for (int mt = 0; mt < 2; mt++)
#pragma unroll
            for (int nt = 0; nt < 4; nt++)
#pragma unroll
                for (int e = 0; e < 4; e++) sacc[mt][nt][e] = 0.f;

#pragma unroll
        for (int ntp = 0; ntp < 2; ntp++) {
            uint32_t kh4[4], kl4[4];
            uint32_t addr = (uint32_t)((kb + ntp * 16 + brow_off) * KROW + bk8 * 2);
            ldm_x4(kh4, khb + addr);
            ldm_x4(kl4, klb + addr);
#pragma unroll
            for (int mt = 0; mt < 2; mt++)
#pragma unroll
                for (int ntl = 0; ntl < 2; ntl++) {
                    int nt = ntp * 2 + ntl;
                    mma_bf16(sacc[mt][nt], qh[mt], &kh4[ntl * 2]);
                    mma_bf16(sacc[mt][nt], qh[mt], &kl4[ntl * 2]);
                    mma_bf16(sacc[mt][nt], ql[mt], &kh4[ntl * 2]);
                }
        }

        // ---- per 16-key chunk: exp + mask + rowsum + pack P, then P*V ----
#pragma unroll
        for (int kcl = 0; kcl < 2; kcl++) {
            uint32_t pph[2][4], ppl[2][4];
#pragma unroll
            for (int mt = 0; mt < 2; mt++) {
#pragma unroll
                for (int kt = 0; kt < 2; kt++) {
                    int nt = kcl * 2 + kt;
                    int c  = kb + nt * 8 + kc0;
                    float p0 = (c     < n) ? __expf(sacc[mt][nt][0]) : 0.f;
                    float p1 = (c + 1 < n) ? __expf(sacc[mt][nt][1]) : 0.f;
                    float p2 = (c     < n) ? __expf(sacc[mt][nt][2]) : 0.f;
                    float p3 = (c + 1 < n) ? __expf(sacc[mt][nt][3]) : 0.f;
                    rs[mt][0] += p0 + p1;
                    rs[mt][1] += p2 + p3;
                    unsigned short h0 = f2bf_us(p0), h1 = f2bf_us(p1);
                    unsigned short h2 = f2bf_us(p2), h3 = f2bf_us(p3);
                    pph[mt][kt * 2]     = (uint32_t)h0 | ((uint32_t)h1 << 16);
                    pph[mt][kt * 2 + 1] = (uint32_t)h2 | ((uint32_t)h3 << 16);
                    ppl[mt][kt * 2]     = bfpack2f(p0 - bf2f_us(h0), p1 - bf2f_us(h1));
                    ppl[mt][kt * 2 + 1] = bfpack2f(p2 - bf2f_us(h2), p3 - bf2f_us(h3));
                }
            }
            // V B-frags via TRANSPOSING ldmatrix from [key][d] layout:
            //   r0=(d0-7,key0-7) r1=(d0-7,key8-15) r2=(d8-15,key0-7) r3=(d8-15,key8-15)
            uint32_t vh4[4], vl4[4];
            uint32_t vaddr = (uint32_t)((kb + kcl * 16 + vrow_off) * KROW + vd16);
            ldm_x4_trans(vh4, vhb + vaddr);
            ldm_x4_trans(vl4, vlb + vaddr);
#pragma unroll
            for (int mt = 0; mt < 2; mt++)
#pragma unroll
                for (int dt = 0; dt < 2; dt++) {
                    mma_bf16(oacc[mt][dt], pph[mt], &vh4[dt * 2]);
                    mma_bf16(oacc[mt][dt], pph[mt], &vl4[dt * 2]);
                    mma_bf16(oacc[mt][dt], ppl[mt], &vh4[dt * 2]);
                }
        }
    }

    // ---- rowsum reduce (quad) + normalize + bf16 hi/lo store ----
#pragma unroll
    for (int mt = 0; mt < 2; mt++)
#pragma unroll
        for (int i = 0; i < 2; i++) {
            float v = rs[mt][i];
            v += __shfl_xor_sync(0xffffffffu, v, 1);
            v += __shfl_xor_sync(0xffffffffu, v, 2);
            rs[mt][i] = 1.f / v;
        }
#pragma unroll
    for (int mt = 0; mt < 2; mt++) {
#pragma unroll
        for (int rr = 0; rr < 2; rr++) {
            int row = qbase + mt * 16 + r0l + rr * 8;
            if (row >= n) continue;
            float li = rs[mt][rr];
#pragma unroll
            for (int dt = 0; dt < 2; dt++) {
                float e0 = oacc[mt][dt][rr * 2]     * li;
                float e1 = oacc[mt][dt][rr * 2 + 1] * li;
                unsigned short h0 = f2bf_us(e0), h1 = f2bf_us(e1);
                uint32_t hp = (uint32_t)h0 | ((uint32_t)h1 << 16);
                uint32_t lp = bfpack2f(e0 - bf2f_us(h0), e1 - bf2f_us(h1));
                size_t base = (size_t)(o + row) * 128 + h * 16 + dt * 8 + kc0;
                *(uint32_t*)((char*)Oh + base * 2) = hp;
                *(uint32_t*)((char*)Ol + base * 2) = lp;
            }
        }
    }
}

// ---------------------------------------------------------------------------
extern "C" void kernel_launch(void* const* d_in, const int* in_sizes, int n_in,
                              void* d_out, int out_size)
{
    const float* att_in = (const float*)d_in[0];
    const float* in_w   = (const float*)d_in[1];
    const float* in_b   = (const float*)d_in[2];
    const float* out_w  = (const float*)d_in[3];
    const float* out_b  = (const float*)d_in[4];
    const int*   agents = (const int*)d_in[5];

    const int T = in_sizes[0] / 128;
    const int B = in_sizes[5];
    float* out  = (float*)d_out;

    float *qkv = nullptr;
    __nv_bfloat16 *ah, *al, *oh, *ol, *wh1, *wl1, *wh2, *wl2;
    cudaGetSymbolAddress((void**)&qkv, g_qkv);
    cudaGetSymbolAddress((void**)&ah,  g_ah);
    cudaGetSymbolAddress((void**)&al,  g_al);
    cudaGetSymbolAddress((void**)&oh,  g_oh);
    cudaGetSymbolAddress((void**)&ol,  g_ol);
    cudaGetSymbolAddress((void**)&wh1, g_wh1);
    cudaGetSymbolAddress((void**)&wl1, g_wl1);
    cudaGetSymbolAddress((void**)&wh2, g_wh2);
    cudaGetSymbolAddress((void**)&wl2, g_wl2);

    cudaFuncSetAttribute(gemm_tc_kernel, cudaFuncAttributeMaxDynamicSharedMemorySize, GEMM_SMEM);
    cudaFuncSetAttribute(attn_kernel, cudaFuncAttributeMaxDynamicSharedMemorySize, ATTN_SMEM);

    // prep: activation planes + weight planes + scan (one launch)
    const int nact = (T * 32 + 255) / 256;
    prep_kernel<<<nact + 65, 256>>>(att_in, in_w, out_w, agents, B, T, nact);

    const int ntiles = T / 64;

    // QKV GEMM: persistent, 49 x 3 CTAs (one 1-CTA/SM wave)
    dim3 g1(49, 3);
    gemm_tc_kernel<<<g1, 256, GEMM_SMEM>>>(ah, al, wh1, wl1, in_b, qkv, 384, ntiles);

    // attention (tensor core, trans-V) -> bf16 hi/lo planes
    attn_kernel<<<B, 512, ATTN_SMEM>>>(qkv, oh, ol, agents, B);

    // out_proj GEMM: persistent, 148 CTAs
    dim3 g2(148, 1);
    gemm_tc_kernel<<<g2, 256, GEMM_SMEM>>>(oh, ol, wh2, wl2, out_b, out, 128, ntiles);
}

// round 17
// speedup vs baseline: 1.0938x; 1.0938x over previous
#include <cuda_runtime.h>
#include <cuda_bf16.h>
#include <cstdint>

typedef unsigned long long ull;

#define MAXT 66560
#define MAXB 2048

// Scratch (static device allocations — no cudaMalloc allowed)
__device__ float         g_qkv[(size_t)MAXT * 384];
__device__ __nv_bfloat16 g_ah[(size_t)MAXT * 128];
__device__ __nv_bfloat16 g_al[(size_t)MAXT * 128];
__device__ __nv_bfloat16 g_oh[(size_t)MAXT * 128];
__device__ __nv_bfloat16 g_ol[(size_t)MAXT * 128];
__device__ __nv_bfloat16 g_wh1[384 * 128];
__device__ __nv_bfloat16 g_wl1[384 * 128];
__device__ __nv_bfloat16 g_wh2[128 * 128];
__device__ __nv_bfloat16 g_wl2[128 * 128];
__device__ int           g_offs[MAXB];

// ---------------------------------------------------------------------------
// f32x2 helpers (attention)
// ---------------------------------------------------------------------------
__device__ __forceinline__ ull pack2(float lo, float hi) {
    ull r;
    asm("mov.b64 %0, {%1, %2};" : "=l"(r)
        : "r"(__float_as_uint(lo)), "r"(__float_as_uint(hi)));
    return r;
}
__device__ __forceinline__ ull ffma2(ull a, ull b, ull c) {
    ull d;
    asm("fma.rn.f32x2 %0, %1, %2, %3;" : "=l"(d) : "l"(a), "l"(b), "l"(c));
    return d;
}
__device__ __forceinline__ ull mul2(ull a, ull b) {
    ull d;
    asm("mul.rn.f32x2 %0, %1, %2;" : "=l"(d) : "l"(a), "l"(b));
    return d;
}
__device__ __forceinline__ ull add2(ull a, ull b) {
    ull d;
    asm("add.rn.f32x2 %0, %1, %2;" : "=l"(d) : "l"(a), "l"(b));
    return d;
}
__device__ __forceinline__ float lo2(ull v) { return __uint_as_float((unsigned)(v & 0xffffffffull)); }
__device__ __forceinline__ float hi2(ull v) { return __uint_as_float((unsigned)(v >> 32)); }
__device__ __forceinline__ float hadd2(ull v) { return lo2(v) + hi2(v); }

__device__ __forceinline__ uint32_t smem_u32(const void* p) {
    uint32_t a;
    asm("{ .reg .u64 t; cvta.to.shared.u64 t, %1; cvt.u32.u64 %0, t; }" : "=r"(a) : "l"(p));
    return a;
}
__device__ __forceinline__ void cp16(uint32_t s, const void* g) {
    asm volatile("cp.async.ca.shared.global [%0], [%1], 16;" :: "r"(s), "l"(g));
}
#define CP_COMMIT() asm volatile("cp.async.commit_group;" ::: "memory")
#define CP_WAIT0()  asm volatile("cp.async.wait_group 0;" ::: "memory")
#define CP_WAIT1()  asm volatile("cp.async.wait_group 1;" ::: "memory")

// bf16 hi/lo split of a float4 -> two packed 8-byte values
__device__ __forceinline__ void split4(float4 v, ull& hp, ull& lp) {
    __nv_bfloat16 hx = __float2bfloat16(v.x), hy = __float2bfloat16(v.y),
                  hz = __float2bfloat16(v.z), hw = __float2bfloat16(v.w);
    hp = (ull)__bfloat16_as_ushort(hx) | ((ull)__bfloat16_as_ushort(hy) << 16)
       | ((ull)__bfloat16_as_ushort(hz) << 32) | ((ull)__bfloat16_as_ushort(hw) << 48);
    __nv_bfloat16 lx = __float2bfloat16(v.x - __bfloat162float(hx));
    __nv_bfloat16 ly = __float2bfloat16(v.y - __bfloat162float(hy));
    __nv_bfloat16 lz = __float2bfloat16(v.z - __bfloat162float(hz));
    __nv_bfloat16 lw = __float2bfloat16(v.w - __bfloat162float(hw));
    lp = (ull)__bfloat16_as_ushort(lx) | ((ull)__bfloat16_as_ushort(ly) << 16)
       | ((ull)__bfloat16_as_ushort(lz) << 32) | ((ull)__bfloat16_as_ushort(lw) << 48);
}

// ---------------------------------------------------------------------------
// Prep kernel (ONE launch):
//   blocks [0, nact)          : convert att_in fp32 -> g_ah/g_al planes
//   blocks [nact, nact+48)    : convert in_proj_w   -> g_wh1/g_wl1
//   blocks [nact+48, nact+64) : convert out_proj_w  -> g_wh2/g_wl2
//   block  nact+64            : exclusive prefix sum -> g_offs
// ---------------------------------------------------------------------------
__global__ void prep_kernel(const float* __restrict__ att_in,
                            const float* __restrict__ w1,
                            const float* __restrict__ w2,
                            const int* __restrict__ agents, int B, int T,
                            int nact)
{
    int bid = blockIdx.x;
    int tid = threadIdx.x;

    if (bid < nact) {
        int i = bid * 256 + tid;
        if (i < T * 32) {
            float4 v = ((const float4*)att_in)[i];
            ull hp, lp;
            split4(v, hp, lp);
            *(ull*)(g_ah + (size_t)i * 4) = hp;
            *(ull*)(g_al + (size_t)i * 4) = lp;
        }
        return;
    }
    int wb = bid - nact;
    if (wb < 64) {
        const float* src;
        __nv_bfloat16 *dh, *dl;
        int i;
        if (wb < 48) {
            src = w1; dh = g_wh1; dl = g_wl1;
            i = wb * 256 + tid;
        } else {
            src = w2; dh = g_wh2; dl = g_wl2;
            i = (wb - 48) * 256 + tid;
        }
        float4 v = ((const float4*)src)[i];
        ull hp, lp;
        split4(v, hp, lp);
        *(ull*)(dh + (size_t)i * 4) = hp;
        *(ull*)(dl + (size_t)i * 4) = lp;
        return;
    }

    // ---- scan ----
    __shared__ int part[256];
    int local[8];
    int s = 0;
#pragma unroll
    for (int i = 0; i < 8; i++) {
        int idx = tid * 8 + i;
        local[i] = (idx < B) ? agents[idx] : 0;
        s += local[i];
    }
    part[tid] = s;
    __syncthreads();
    for (int d = 1; d < 256; d <<= 1) {
        int v = (tid >= d) ? part[tid - d] : 0;
        __syncthreads();
        part[tid] += v;
        __syncthreads();
    }
    int base = (tid > 0) ? part[tid - 1] : 0;
#pragma unroll
    for (int i = 0; i < 8; i++) {
        int idx = tid * 8 + i;
        if (idx < B) g_offs[idx] = base;
        base += local[i];
    }
}

// ---------------------------------------------------------------------------
// Persistent GEMM v9: r12 config (64x128 CTA tile, W resident, double-buffered
// A tiles) + SOFTWARE-PIPELINED FRAGMENTS: LDSM for k+1 issued before the
// 24 HMMA of step k, hiding the ~30cyc LDSM latency under HMMA dispatch.
// 3-term split: Ah*Wh + Ah*Wl + Al*Wh.
// ---------------------------------------------------------------------------
#define ASTRIDE 136                  // bf16 elems per smem row (272B)
#define SA0_H 0
#define SA0_L 17408
#define SA1_H 34816
#define SA1_L 52224
#define SW_H  69632
#define SW_L  104448
#define GEMM_SMEM 139264

__device__ __forceinline__ void ldm_x4(uint32_t* r, uint32_t addr) {
    asm volatile("ldmatrix.sync.aligned.m8n8.x4.shared.b16 {%0,%1,%2,%3}, [%4];"
                 : "=r"(r[0]), "=r"(r[1]), "=r"(r[2]), "=r"(r[3]) : "r"(addr));
}
__device__ __forceinline__ void mma_bf16(float* d, const uint32_t* a, const uint32_t* b) {
    asm volatile("mma.sync.aligned.m16n8k16.row.col.f32.bf16.bf16.f32 "
                 "{%0,%1,%2,%3}, {%4,%5,%6,%7}, {%8,%9}, {%0,%1,%2,%3};"
                 : "+f"(d[0]), "+f"(d[1]), "+f"(d[2]), "+f"(d[3])
                 : "r"(a[0]), "r"(a[1]), "r"(a[2]), "r"(a[3]), "r"(b[0]), "r"(b[1]));
}

__device__ __forceinline__ void fill_a(uint32_t sb, uint32_t off_h, uint32_t off_l,
                                       const __nv_bfloat16* Ah, const __nv_bfloat16* Al,
                                       int bm, int tid)
{
#pragma unroll
    for (int t = 0; t < 4; t++) {
        int c = tid + t * 256;           // 0..1023
        int row = c >> 4, c16 = c & 15;
        uint32_t so = (uint32_t)(row * 272 + c16 * 16);
        cp16(sb + off_h + so, (const char*)(Ah + (size_t)(bm + row) * 128) + c16 * 16);
        cp16(sb + off_l + so, (const char*)(Al + (size_t)(bm + row) * 128) + c16 * 16);
    }
}

__global__ __launch_bounds__(256) void gemm_tc_kernel(
    const __nv_bfloat16* __restrict__ Ah_g, const __nv_bfloat16* __restrict__ Al_g,
    const __nv_bfloat16* __restrict__ Wh, const __nv_bfloat16* __restrict__ Wl,
    const float* __restrict__ bias, float* __restrict__ C, int N, int ntiles)
{
    extern __shared__ char sm[];
    const uint32_t sb = smem_u32(sm);
    const int tid  = threadIdx.x;
    const int wid  = tid >> 5;
    const int lane = tid & 31;
    const int bn   = blockIdx.y * 128;
    const int t0     = blockIdx.x;
    const int stride = gridDim.x;

    // ---- W slice (128 rows, hi+lo) once ----
#pragma unroll
    for (int t = 0; t < 8; t++) {
        int c = tid + t * 256;           // 0..2047
        int row = c >> 4, c16 = c & 15;
        uint32_t so = (uint32_t)(row * 272 + c16 * 16);
        cp16(sb + SW_H + so, (const char*)(Wh + (size_t)(bn + row) * 128) + c16 * 16);
        cp16(sb + SW_L + so, (const char*)(Wl + (size_t)(bn + row) * 128) + c16 * 16);
    }
    if (t0 < ntiles)
        fill_a(sb, SA0_H, SA0_L, Ah_g, Al_g, t0 * 64, tid);
    CP_COMMIT();

    const int wm = (wid & 1) * 32;
    const int wn = (wid >> 1) * 32;
    const int arow = wm + (lane & 15);
    const int acol8 = (lane >> 4) * 8;
    const int bgrp = lane >> 3;
    const int brow0 = wn + ((bgrp >> 1) << 3) + (lane & 7);
    const int bk8   = (bgrp & 1) << 3;
    const int er = lane >> 2;
    const int ec = (lane & 3) * 2;

    float bb0[4], bb1[4];
#pragma unroll
    for (int ni = 0; ni < 4; ni++) {
        int n = bn + wn + ni * 8 + ec;
        bb0[ni] = bias[n];
        bb1[ni] = bias[n + 1];
    }

    // fragment byte offsets (k enters as +32*k bytes)
    const uint32_t a_off0 = (uint32_t)((arow * ASTRIDE + acol8) * 2);
    const uint32_t a_off1 = (uint32_t)(((arow + 16) * ASTRIDE + acol8) * 2);
    const uint32_t b_off0 = (uint32_t)((brow0 * ASTRIDE + bk8) * 2);
    const uint32_t b_off1 = (uint32_t)(((brow0 + 16) * ASTRIDE + bk8) * 2);

    int buf = 0;
    for (int t = t0; t < ntiles; t += stride) {
        int tn = t + stride;
        if (tn < ntiles) {
            fill_a(sb, buf ? SA0_H : SA1_H, buf ? SA0_L : SA1_L,
                   Ah_g, Al_g, tn * 64, tid);
            CP_COMMIT();
            CP_WAIT1();
        } else {
            CP_WAIT0();
        }
        __syncthreads();

        const uint32_t sa_h = sb + (buf ? SA1_H : SA0_H);
        const uint32_t sa_l = sb + (buf ? SA1_L : SA0_L);
        const uint32_t sw_h = sb + SW_H;
        const uint32_t sw_l = sb + SW_L;

        float acc[2][4][4];
#pragma unroll
        for (int mi = 0; mi < 2; mi++)
#pragma unroll
            for (int ni = 0; ni < 4; ni++)
#pragma unroll
                for (int e = 0; e < 4; e++) acc[mi][ni][e] = 0.f;

        // double-buffered fragments: [pipebuf][...]
        uint32_t ahf[2][2][4], alf[2][2][4];
        uint32_t bhf[2][4][2], blf[2][4][2];

        // preload k = 0 into pipe buffer 0
        ldm_x4(ahf[0][0], sa_h + a_off0);
        ldm_x4(ahf[0][1], sa_h + a_off1);
        ldm_x4(alf[0][0], sa_l + a_off0);
        ldm_x4(alf[0][1], sa_l + a_off1);
        ldm_x4(&bhf[0][0][0], sw_h + b_off0);
        ldm_x4(&bhf[0][2][0], sw_h + b_off1);
        ldm_x4(&blf[0][0][0], sw_l + b_off0);
        ldm_x4(&blf[0][2][0], sw_l + b_off1);

#pragma unroll
        for (int k = 0; k < 8; k++) {
            const int cur = k & 1;
            const int nxt = cur ^ 1;
            if (k < 7) {
                const uint32_t kb = (uint32_t)((k + 1) * 32);   // bytes
                ldm_x4(ahf[nxt][0], sa_h + a_off0 + kb);
                ldm_x4(ahf[nxt][1], sa_h + a_off1 + kb);
                ldm_x4(alf[nxt][0], sa_l + a_off0 + kb);
                ldm_x4(alf[nxt][1], sa_l + a_off1 + kb);
                ldm_x4(&bhf[nxt][0][0], sw_h + b_off0 + kb);
                ldm_x4(&bhf[nxt][2][0], sw_h + b_off1 + kb);
                ldm_x4(&blf[nxt][0][0], sw_l + b_off0 + kb);
                ldm_x4(&blf[nxt][2][0], sw_l + b_off1 + kb);
            }
#pragma unroll
            for (int mi = 0; mi < 2; mi++)
#pragma unroll
                for (int ni = 0; ni < 4; ni++) {
                    mma_bf16(acc[mi][ni], ahf[cur][mi], bhf[cur][ni]);
                    mma_bf16(acc[mi][ni], ahf[cur][mi], blf[cur][ni]);
                    mma_bf16(acc[mi][ni], alf[cur][mi], bhf[cur][ni]);
                }
        }

        const int bm = t * 64;
#pragma unroll
        for (int ni = 0; ni < 4; ni++) {
            int n = bn + wn + ni * 8 + ec;
#pragma unroll
            for (int mi = 0; mi < 2; mi++) {
                int m0 = bm + wm + mi * 16 + er;
                *(float2*)(C + (size_t)m0 * N + n) =
                    make_float2(acc[mi][ni][0] + bb0[ni], acc[mi][ni][1] + bb1[ni]);
                *(float2*)(C + (size_t)(m0 + 8) * N + n) =
                    make_float2(acc[mi][ni][2] + bb0[ni], acc[mi][ni][3] + bb1[ni]);
            }
        }
        __syncthreads();
        buf ^= 1;
    }
}

// ---------------------------------------------------------------------------
// Attention (r11/r12 proven): block per sample, warp per head (fill K/V once,
// __syncwarp only), query halves processed sequentially. Writes bf16 hi/lo
// output planes (fuses out_proj input conversion).
// ---------------------------------------------------------------------------
__device__ __forceinline__ void store_bf_split(
    __nv_bfloat16* __restrict__ Oh, __nv_bfloat16* __restrict__ Ol,
    size_t base, const ull* ov, float linv)
{
    ull inv = pack2(linv, linv);
#pragma unroll
    for (int t = 0; t < 4; t++) {
        ull r0 = mul2(ov[2 * t], inv);
        ull r1 = mul2(ov[2 * t + 1], inv);
        float4 f = make_float4(lo2(r0), hi2(r0), lo2(r1), hi2(r1));
        ull hp, lp;
        split4(f, hp, lp);
        *(ull*)(Oh + base + t * 4) = hp;
        *(ull*)(Ol + base + t * 4) = lp;
    }
}

__global__ __launch_bounds__(256, 3) void attn_kernel(
    const float* __restrict__ Y,            // qkv [T][384]
    __nv_bfloat16* __restrict__ Oh,         // attn out hi plane [T][128]
    __nv_bfloat16* __restrict__ Ol,         // attn out lo plane [T][128]
    const int* __restrict__ agents, int B)
{
    extern __shared__ float smf[];       // 8 warps * (1024 K + 1024 V) floats
    int b = blockIdx.x;
    if (B == 2048) {
        int g = b >> 5, k = b & 31;
        b = (k << 6) + (63 - g);
    }
    const int n    = agents[b];
    const int o    = g_offs[b];
    const int tid  = threadIdx.x;
    const int w    = tid >> 5;           // head index
    const int lane = tid & 31;

    float* Ks = smf + w * 2048;
    float* Vs = Ks + 1024;

    int nseg = n * 4;
    for (int si = lane; si < nseg; si += 32) {
        int r = si >> 2, s = si & 3;
        const float* base = Y + (size_t)(o + r) * 384 + w * 16 + s * 4;
        *(float4*)(Ks + r * 16 + s * 4) = *(const float4*)(base + 128);
        *(float4*)(Vs + r * 16 + s * 4) = *(const float4*)(base + 256);
    }
    __syncwarp();

    const ull QSC = pack2(0.25f, 0.25f);
    const int nhalves = (n > 32) ? 2 : 1;

    for (int half = 0; half < nhalves; half++) {
        const int i0 = half * 32 + lane;
        const bool valid = i0 < n;

        ull q0[8];
#pragma unroll
        for (int d = 0; d < 8; d++) q0[d] = 0ull;
        if (valid) {
            const float4* qp = (const float4*)(Y + (size_t)(o + i0) * 384 + w * 16);
#pragma unroll
            for (int t = 0; t < 4; t++) {
                float4 v = qp[t];
                q0[t * 2 + 0] = mul2(pack2(v.x, v.y), QSC);
                q0[t * 2 + 1] = mul2(pack2(v.z, v.w), QSC);
            }
        }

        ull o0[8];
#pragma unroll
        for (int d = 0; d < 8; d++) o0[d] = 0ull;
        float l0 = 0.f;

#pragma unroll 2
        for (int j = 0; j < n; j++) {
            const ulonglong2* kp = (const ulonglong2*)(Ks + j * 16);
            ulonglong2 k01 = kp[0], k23 = kp[1], k45 = kp[2], k67 = kp[3];

            ull saA = 0, saB = 0;
            saA = ffma2(q0[0], k01.x, saA);
            saB = ffma2(q0[1], k01.y, saB);
            saA = ffma2(q0[2], k23.x, saA);
            saB = ffma2(q0[3], k23.y, saB);
            saA = ffma2(q0[4], k45.x, saA);
            saB = ffma2(q0[5], k45.y, saB);
            saA = ffma2(q0[6], k67.x, saA);
            saB = ffma2(q0[7], k67.y, saB);

            float e0 = __expf(hadd2(add2(saA, saB)));
            l0 += e0;
            ull e00 = pack2(e0, e0);

            const ulonglong2* vp = (const ulonglong2*)(Vs + j * 16);
            ulonglong2 v01 = vp[0], v23 = vp[1], v45 = vp[2], v67 = vp[3];
            o0[0] = ffma2(e00, v01.x, o0[0]);
            o0[1] = ffma2(e00, v01.y, o0[1]);
            o0[2] = ffma2(e00, v23.x, o0[2]);
            o0[3] = ffma2(e00, v23.y, o0[3]);
            o0[4] = ffma2(e00, v45.x, o0[4]);
            o0[5] = ffma2(e00, v45.y, o0[5]);
            o0[6] = ffma2(e00, v67.x, o0[6]);
            o0[7] = ffma2(e00, v67.y, o0[7]);
        }

        if (valid)
            store_bf_split(Oh, Ol, (size_t)(o + i0) * 128 + w * 16, o0, 1.f / l0);
    }
}

// ---------------------------------------------------------------------------
extern "C" void kernel_launch(void* const* d_in, const int* in_sizes, int n_in,
                              void* d_out, int out_size)
{
    const float* att_in = (const float*)d_in[0];
    const float* in_w   = (const float*)d_in[1];
    const float* in_b   = (const float*)d_in[2];
    const float* out_w  = (const float*)d_in[3];
    const float* out_b  = (const float*)d_in[4];
    const int*   agents = (const int*)d_in[5];

    const int T = in_sizes[0] / 128;
    const int B = in_sizes[5];
    float* out  = (float*)d_out;

    float *qkv = nullptr;
    __nv_bfloat16 *ah, *al, *oh, *ol, *wh1, *wl1, *wh2, *wl2;
    cudaGetSymbolAddress((void**)&qkv, g_qkv);
    cudaGetSymbolAddress((void**)&ah,  g_ah);
    cudaGetSymbolAddress((void**)&al,  g_al);
    cudaGetSymbolAddress((void**)&oh,  g_oh);
    cudaGetSymbolAddress((void**)&ol,  g_ol);
    cudaGetSymbolAddress((void**)&wh1, g_wh1);
    cudaGetSymbolAddress((void**)&wl1, g_wl1);
    cudaGetSymbolAddress((void**)&wh2, g_wh2);
    cudaGetSymbolAddress((void**)&wl2, g_wl2);

    cudaFuncSetAttribute(gemm_tc_kernel, cudaFuncAttributeMaxDynamicSharedMemorySize, GEMM_SMEM);
    cudaFuncSetAttribute(attn_kernel, cudaFuncAttributeMaxDynamicSharedMemorySize, 65536);

    // prep: activation planes + weight planes + scan (one launch)
    const int nact = (T * 32 + 255) / 256;
    prep_kernel<<<nact + 65, 256>>>(att_in, in_w, out_w, agents, B, T, nact);

    const int ntiles = T / 64;

    // QKV GEMM: persistent, 49 x 3 CTAs (one 1-CTA/SM wave)
    dim3 g1(49, 3);
    gemm_tc_kernel<<<g1, 256, GEMM_SMEM>>>(ah, al, wh1, wl1, in_b, qkv, 384, ntiles);

    // attention -> bf16 hi/lo planes
    attn_kernel<<<B, 256, 65536>>>(qkv, oh, ol, agents, B);

    // out_proj GEMM: persistent, 148 CTAs
    dim3 g2(148, 1);
    gemm_tc_kernel<<<g2, 256, GEMM_SMEM>>>(oh, ol, wh2, wl2, out_b, out, 128, ntiles);
}